// round 17
// baseline (speedup 1.0000x reference)
#include <cuda_runtime.h>
#include <cuda_fp16.h>
#include <math.h>
#include <stdint.h>

#define NN   100000
#define NE   250000
#define NB   2000
#define FIN  75
#define DIM  32
#define HID  128
#define NOUT 1024           // DIM*DIM
#define MPAD 250112         // 3908 * 64

// ---------------- scratch (static __device__, no allocation) ----------------
__device__ __align__(16) __half g_ewb[(size_t)MPAD * NOUT];  // edge weights fp16, [o][i] per edge
__device__ __align__(16) __half g_w2b[NOUT * HID];           // W2 fp16, column-permuted (c' = o*32+i)
__device__ __align__(16) __half g_gruB[128 * 64];            // GRU combined weights [128 x 64] fp16
__device__ float g_b2p[NOUT];                                // b2 permuted
__device__ float g_x[NN * DIM];                 // node state
__device__ float g_acc[NN * DIM];               // conv scatter accumulator
__device__ int   g_cnt[NN];                     // in-degree
// transposed weights
__device__ float g_w0T[FIN * DIM];
__device__ float g_w1T[11 * HID];
__device__ float g_lwihT[64 * 128];
__device__ float g_lwhhT[DIM * 128];

__device__ __forceinline__ uint32_t smem_u32(const void* p) {
    uint32_t a;
    asm("{ .reg .u64 t; cvta.to.shared.u64 t, %1; cvt.u32.u64 %0, t; }" : "=r"(a) : "l"(p));
    return a;
}
__device__ __forceinline__ void cp_async16(uint32_t dst, const void* src) {
    asm volatile("cp.async.cg.shared.global [%0], [%1], 16;" :: "r"(dst), "l"(src));
}
#define CP_COMMIT() asm volatile("cp.async.commit_group;" ::: "memory")
#define CP_WAIT0()  asm volatile("cp.async.wait_group 0;" ::: "memory")

__device__ __forceinline__ void mma_fp16(float* c, const uint32_t* a, uint32_t b0, uint32_t b1) {
    asm volatile(
        "mma.sync.aligned.m16n8k16.row.col.f32.f16.f16.f32 "
        "{%0,%1,%2,%3}, {%4,%5,%6,%7}, {%8,%9}, {%0,%1,%2,%3};"
        : "+f"(c[0]), "+f"(c[1]), "+f"(c[2]), "+f"(c[3])
        : "r"(a[0]), "r"(a[1]), "r"(a[2]), "r"(a[3]), "r"(b0), "r"(b1));
}

// ---------------- prep: transposes + fp16 W2 (col-permuted) + GRU combined B ----------------
__global__ void prep_kernel(const float* __restrict__ w0, const float* __restrict__ w1,
                            const float* __restrict__ gwih, const float* __restrict__ gwhh,
                            const float* __restrict__ lwih, const float* __restrict__ lwhh,
                            const float* __restrict__ w2, const float* __restrict__ b2) {
    int t = blockIdx.x * 256 + threadIdx.x;
    if (t < FIN * DIM) { int i = t / DIM, o = t % DIM; g_w0T[t] = w0[o * FIN + i]; }
    if (t < 11 * HID)  { int i = t / HID, j = t % HID; g_w1T[t] = w1[j * 11 + i]; }
    if (t < 64 * 128)  { int i = t / 128, r = t % 128; g_lwihT[t] = lwih[r * 64 + i]; }
    if (t < DIM * 128) { int i = t / 128, r = t % 128; g_lwhhT[t] = lwhh[r * DIM + i]; }
    if (t < NOUT) { int corig = (t & 31) * 32 + (t >> 5); g_b2p[t] = b2[corig]; }
    if (t < 128 * 64) {
        int np = t >> 6, k = t & 63;
        float v = 0.f;
        int o = np & 31, blk = np >> 5;       // blk: 0=r-sum 1=z-sum 2=gi_n 3=gh_n
        if (blk == 0) v = (k < 32) ? gwih[o * DIM + k]          : gwhh[o * DIM + (k - 32)];
        else if (blk == 1) v = (k < 32) ? gwih[(32 + o) * DIM + k]   : gwhh[(32 + o) * DIM + (k - 32)];
        else if (blk == 2) v = (k < 32) ? gwih[(64 + o) * DIM + k]   : 0.f;
        else               v = (k < 32) ? 0.f                        : gwhh[(64 + o) * DIM + (k - 32)];
        g_gruB[t] = __float2half(v);
    }
    if (t < NOUT * HID) {
        int cp = t / HID, k = t % HID;
        int corig = (cp & 31) * 32 + (cp >> 5);
        g_w2b[t] = __float2half(w2[corig * HID + k]);
    }
}

__global__ void deg_kernel(const int* __restrict__ ei) {
    int e = blockIdx.x * 256 + threadIdx.x;
    if (e < NE) atomicAdd(&g_cnt[ei[NE + e]], 1);
}

// ---------------- lin0: 64 nodes/block, 8 nodes/warp; also zeroes g_cnt / g_acc ----------------
__global__ void __launch_bounds__(256) lin0_kernel(const float* __restrict__ nf,
                                                   const float* __restrict__ b) {
    __shared__ float sf[64][FIN + 1];
    int tid = threadIdx.x;
    int base = blockIdx.x * 64;
    for (int idx = tid; idx < 64 * FIN; idx += 256) {
        int n = idx / FIN, i = idx % FIN;
        int node = base + n;
        sf[n][i] = (node < NN) ? nf[(size_t)node * FIN + i] : 0.f;
    }
    __syncthreads();
    int warp = tid >> 5, o = tid & 31;
    int n0 = warp * 8;
    float acc[8];
    float bo = b[o];
#pragma unroll
    for (int n = 0; n < 8; n++) acc[n] = bo;
    for (int i = 0; i < FIN; i++) {
        float w = g_w0T[i * DIM + o];
#pragma unroll
        for (int n = 0; n < 8; n++) acc[n] = fmaf(sf[n0 + n][i], w, acc[n]);
    }
#pragma unroll
    for (int n = 0; n < 8; n++) {
        int node = base + n0 + n;
        if (node < NN) {
            g_x[node * DIM + o] = fmaxf(acc[n], 0.f);
            g_acc[node * DIM + o] = 0.f;
            if (o == 0) g_cnt[node] = 0;
        }
    }
}

// ---- fused GEMM: per CTA of 64 edges; M=64 tile, 3 CTAs/SM; cp.async B slabs ----
#define SM_A     0                        // 64 x 256B = 16384
#define SM_B     16384                    // 128 x 256B = 32768
#define SM_CSTG  49152                    // 64 x 272B = 17408 (aux overlapped here)
#define SM_SEF   49152                    // 64 x 12 floats = 3072
#define SM_W1T   (49152 + 3072)           // 5632
#define SM_B1    (49152 + 3072 + 5632)    // 512
#define SM_BIAS  66560                    // 1024 floats = 4096
#define SMEM_GEMM_TOTAL 70656
#define CSTRIDE 272

__global__ void __launch_bounds__(256, 3) gemm_fused_kernel(const float* __restrict__ ef,
                                                            const float* __restrict__ b1) {
    extern __shared__ __align__(16) char smem[];
    uint32_t sbase = smem_u32(smem);
    float* sef   = (float*)(smem + SM_SEF);
    float* sw1t  = (float*)(smem + SM_W1T);
    float* sb1   = (float*)(smem + SM_B1);
    float* sbias = (float*)(smem + SM_BIAS);
    int tid = threadIdx.x, lane = tid & 31, wid = tid >> 5;
    int e0 = blockIdx.x * 64;

    // issue cp.async for B slab 0 (overlaps aux loads + A build)
#pragma unroll
    for (int it = 0; it < 8; it++) {
        int idx = tid + it * 256;
        int row = idx >> 4, c = idx & 15;
        int cs = (c & 8) | ((c ^ row) & 7);
        cp_async16(sbase + SM_B + row * 256 + cs * 16,
                   (const char*)g_w2b + (((size_t)row) * HID + c * 8) * 2);
    }
    CP_COMMIT();

    for (int idx = tid; idx < 64 * 11; idx += 256) {
        int r = idx / 11, i = idx % 11;
        int e = e0 + r;
        sef[r * 12 + i] = (e < NE) ? ef[(size_t)e * 11 + i] : 0.f;
    }
    for (int idx = tid; idx < 11 * HID; idx += 256) sw1t[idx] = g_w1T[idx];
    if (tid < 128) sb1[tid] = b1[tid];
#pragma unroll
    for (int l = 0; l < 4; l++) sbias[tid + l * 256] = g_b2p[tid + l * 256];
    __syncthreads();

    // build A tile: hw = relu(ef @ W1^T + b1), fp16, xor-swizzled (64 rows x 16 chunks)
#pragma unroll
    for (int ci = 0; ci < 4; ci++) {
        int cidx = tid + ci * 256;
        int row = cidx >> 4, c = cidx & 15;
        int k0 = c * 8;
        float v[8];
#pragma unroll
        for (int j = 0; j < 8; j++) v[j] = sb1[k0 + j];
#pragma unroll
        for (int i = 0; i < 11; i++) {
            float e_ = sef[row * 12 + i];
#pragma unroll
            for (int j = 0; j < 8; j++) v[j] = fmaf(e_, sw1t[i * HID + k0 + j], v[j]);
        }
        uint32_t p[4];
#pragma unroll
        for (int j = 0; j < 4; j++) {
            __half2 h = __floats2half2_rn(fmaxf(v[2 * j], 0.f), fmaxf(v[2 * j + 1], 0.f));
            p[j] = *(uint32_t*)&h;
        }
        int cs = (c & 8) | ((c ^ row) & 7);
        *(uint4*)(smem + SM_A + row * 256 + cs * 16) = make_uint4(p[0], p[1], p[2], p[3]);
    }
    CP_WAIT0();
    __syncthreads();     // A built, B0 in smem, aux consumed

    int wm = (wid & 1) * 32;     // 2 warps in M
    int wn = (wid >> 1) * 32;    // 4 warps in N
    int g = lane >> 2, tg = lane & 3;

    for (int nb = 0; nb < 8; nb++) {
        float acc[2][4][4];
#pragma unroll
        for (int mb = 0; mb < 2; mb++)
#pragma unroll
            for (int nbb = 0; nbb < 4; nbb++)
#pragma unroll
                for (int q = 0; q < 4; q++) acc[mb][nbb][q] = 0.f;

#pragma unroll
        for (int ks = 0; ks < 8; ks++) {
            int ck0 = ks * 2;
            uint32_t a[2][4], b[2][4];
#pragma unroll
            for (int mb = 0; mb < 2; mb++) {
                int row = wm + mb * 16 + (lane & 7) + ((lane >> 3) & 1) * 8;
                int ck = ck0 + (lane >> 4);
                int cs = (ck & 8) | ((ck ^ row) & 7);
                uint32_t addr = sbase + SM_A + row * 256 + cs * 16;
                asm volatile("ldmatrix.sync.aligned.m8n8.x4.shared.b16 {%0,%1,%2,%3}, [%4];"
                             : "=r"(a[mb][0]), "=r"(a[mb][1]), "=r"(a[mb][2]), "=r"(a[mb][3])
                             : "r"(addr));
            }
#pragma unroll
            for (int nb4 = 0; nb4 < 2; nb4++) {
                int t = lane >> 3, r = lane & 7;
                int n = wn + nb4 * 16 + r + (t >> 1) * 8;
                int ck = ck0 + (t & 1);
                int cs = (ck & 8) | ((ck ^ n) & 7);
                uint32_t addr = sbase + SM_B + n * 256 + cs * 16;
                asm volatile("ldmatrix.sync.aligned.m8n8.x4.shared.b16 {%0,%1,%2,%3}, [%4];"
                             : "=r"(b[nb4][0]), "=r"(b[nb4][1]), "=r"(b[nb4][2]), "=r"(b[nb4][3])
                             : "r"(addr));
            }
#pragma unroll
            for (int mb = 0; mb < 2; mb++)
#pragma unroll
                for (int nbb = 0; nbb < 4; nbb++)
                    mma_fp16(acc[mb][nbb], a[mb], b[nbb >> 1][(nbb & 1) * 2], b[nbb >> 1][(nbb & 1) * 2 + 1]);
        }

        // stage C (register -> CSTG)
#pragma unroll
        for (int mb = 0; mb < 2; mb++)
#pragma unroll
            for (int nbb = 0; nbb < 4; nbb++) {
                int rowl = wm + mb * 16 + g;
                int nl = wn + nbb * 8 + tg * 2;
                float bb0 = sbias[nb * 128 + nl], bb1 = sbias[nb * 128 + nl + 1];
                float* c = acc[mb][nbb];
                __half2 p0 = __floats2half2_rn(c[0] + bb0, c[1] + bb1);
                __half2 p1 = __floats2half2_rn(c[2] + bb0, c[3] + bb1);
                *(uint32_t*)(smem + SM_CSTG + rowl * CSTRIDE + nl * 2) = *(uint32_t*)&p0;
                *(uint32_t*)(smem + SM_CSTG + (rowl + 8) * CSTRIDE + nl * 2) = *(uint32_t*)&p1;
            }
        __syncthreads();   // all mma done (B free), CSTG complete

        // cp.async next B slab — overlaps the global writeback below
        if (nb < 7) {
#pragma unroll
            for (int it = 0; it < 8; it++) {
                int idx = tid + it * 256;
                int row = idx >> 4, c = idx & 15;
                int cs = (c & 8) | ((c ^ row) & 7);
                cp_async16(sbase + SM_B + row * 256 + cs * 16,
                           (const char*)g_w2b + (((size_t)((nb + 1) * 128 + row)) * HID + c * 8) * 2);
            }
            CP_COMMIT();
        }

        __half* dst = g_ewb + (size_t)e0 * NOUT + nb * 128;
#pragma unroll
        for (int it = 0; it < 4; it++) {
            int idx = tid + it * 256;
            int row = idx >> 4, c = idx & 15;
            uint4 v = *(const uint4*)(smem + SM_CSTG + row * CSTRIDE + c * 16);
            *(uint4*)(dst + (size_t)row * NOUT + c * 8) = v;
        }
        if (nb < 7) CP_WAIT0();
        __syncthreads();   // CSTG free; next B ready
    }
}

// ---------------- NNConv: warp per edge, lane = output channel ----------------
__global__ void conv_kernel(const int* __restrict__ ei) {
    int e = blockIdx.x * 8 + (threadIdx.x >> 5);
    if (e >= NE) return;
    int o = threadIdx.x & 31;
    int src = ei[e];
    int dst = ei[NE + e];
    float xv = g_x[src * DIM + o];
    const uint4* w = (const uint4*)(g_ewb + (size_t)e * NOUT + o * 32);
    uint4 w0 = w[0], w1 = w[1], w2 = w[2], w3 = w[3];
    uint32_t ws[16] = {w0.x, w0.y, w0.z, w0.w, w1.x, w1.y, w1.z, w1.w,
                       w2.x, w2.y, w2.z, w2.w, w3.x, w3.y, w3.z, w3.w};
    float acc = 0.f;
#pragma unroll
    for (int i = 0; i < 16; i++) {
        float2 wp = __half22float2(*(__half2*)&ws[i]);
        float x0 = __shfl_sync(0xffffffffu, xv, 2 * i);
        float x1 = __shfl_sync(0xffffffffu, xv, 2 * i + 1);
        acc = fmaf(x0, wp.x, fmaf(x1, wp.y, acc));
    }
    atomicAdd(&g_acc[dst * DIM + o], acc);
}

// ---------------- GRU via mma: 64 nodes/block, gates = [m|h] @ W'^T ----------------
#define GSA   0
#define GSB   8192
#define GSHF  24576
#define GSD   32768
#define GRU_SMEM (32768 + 64 * 132 * 4)   // 66560

__global__ void __launch_bounds__(256) gru_mma_kernel(const float* __restrict__ cbias,
                                                      const float* __restrict__ bih,
                                                      const float* __restrict__ bhh) {
    extern __shared__ __align__(16) char smem[];
    uint32_t sbase = smem_u32(smem);
    float* shf = (float*)(smem + GSHF);
    float* sD  = (float*)(smem + GSD);
    int tid = threadIdx.x, lane = tid & 31, wid = tid >> 5;
    int base = blockIdx.x * 64;

#pragma unroll
    for (int l = 0; l < 4; l++) {
        int idx = tid + l * 256;
        int row = idx >> 3, c = idx & 7;
        int cs = c ^ (row & 7);
        *(uint4*)(smem + GSB + row * 128 + cs * 16) = ((const uint4*)g_gruB)[idx];
    }
#pragma unroll
    for (int l = 0; l < 2; l++) {
        int idx = tid + l * 256;
        int n = idx >> 3, c = idx & 7;
        int node = base + n;
        float v[8];
        if (node < NN) {
            if (c < 4) {
                int k0 = c * 8;
                float4 a0 = *(float4*)&g_acc[node * DIM + k0];
                float4 a1 = *(float4*)&g_acc[node * DIM + k0 + 4];
                float4 cb0 = *(const float4*)&cbias[k0];
                float4 cb1 = *(const float4*)&cbias[k0 + 4];
                int cnt = g_cnt[node]; if (cnt < 1) cnt = 1;
                float fc = (float)cnt;
                v[0] = fmaxf(a0.x / fc + cb0.x, 0.f);
                v[1] = fmaxf(a0.y / fc + cb0.y, 0.f);
                v[2] = fmaxf(a0.z / fc + cb0.z, 0.f);
                v[3] = fmaxf(a0.w / fc + cb0.w, 0.f);
                v[4] = fmaxf(a1.x / fc + cb1.x, 0.f);
                v[5] = fmaxf(a1.y / fc + cb1.y, 0.f);
                v[6] = fmaxf(a1.z / fc + cb1.z, 0.f);
                v[7] = fmaxf(a1.w / fc + cb1.w, 0.f);
                *(float4*)&g_acc[node * DIM + k0]     = make_float4(0.f, 0.f, 0.f, 0.f);
                *(float4*)&g_acc[node * DIM + k0 + 4] = make_float4(0.f, 0.f, 0.f, 0.f);
            } else {
                int k0 = (c - 4) * 8;
                float4 h0 = *(float4*)&g_x[node * DIM + k0];
                float4 h1 = *(float4*)&g_x[node * DIM + k0 + 4];
                v[0] = h0.x; v[1] = h0.y; v[2] = h0.z; v[3] = h0.w;
                v[4] = h1.x; v[5] = h1.y; v[6] = h1.z; v[7] = h1.w;
                *(float4*)&shf[n * 32 + k0]     = h0;
                *(float4*)&shf[n * 32 + k0 + 4] = h1;
            }
        } else {
#pragma unroll
            for (int j = 0; j < 8; j++) v[j] = 0.f;
            if (c >= 4) {
                int k0 = (c - 4) * 8;
                *(float4*)&shf[n * 32 + k0]     = make_float4(0.f, 0.f, 0.f, 0.f);
                *(float4*)&shf[n * 32 + k0 + 4] = make_float4(0.f, 0.f, 0.f, 0.f);
            }
        }
        uint32_t p[4];
#pragma unroll
        for (int j = 0; j < 4; j++) {
            __half2 h = __floats2half2_rn(v[2 * j], v[2 * j + 1]);
            p[j] = *(uint32_t*)&h;
        }
        int cs = c ^ (n & 7);
        *(uint4*)(smem + GSA + n * 128 + cs * 16) = make_uint4(p[0], p[1], p[2], p[3]);
    }
    __syncthreads();

    int wm = (wid & 3) * 16;
    int wn = (wid >> 2) * 64;
    float acc[8][4];
#pragma unroll
    for (int nbb = 0; nbb < 8; nbb++)
#pragma unroll
        for (int q = 0; q < 4; q++) acc[nbb][q] = 0.f;

#pragma unroll
    for (int ks = 0; ks < 4; ks++) {
        int ck0 = ks * 2;
        uint32_t a[4], b[4][4];
        {
            int row = wm + (lane & 7) + ((lane >> 3) & 1) * 8;
            int ck = ck0 + (lane >> 4);
            int cs = ck ^ (row & 7);
            uint32_t addr = sbase + GSA + row * 128 + cs * 16;
            asm volatile("ldmatrix.sync.aligned.m8n8.x4.shared.b16 {%0,%1,%2,%3}, [%4];"
                         : "=r"(a[0]), "=r"(a[1]), "=r"(a[2]), "=r"(a[3]) : "r"(addr));
        }
#pragma unroll
        for (int nb4 = 0; nb4 < 4; nb4++) {
            int t = lane >> 3, r = lane & 7;
            int n = wn + nb4 * 16 + r + (t >> 1) * 8;
            int ck = ck0 + (t & 1);
            int cs = ck ^ (n & 7);
            uint32_t addr = sbase + GSB + n * 128 + cs * 16;
            asm volatile("ldmatrix.sync.aligned.m8n8.x4.shared.b16 {%0,%1,%2,%3}, [%4];"
                         : "=r"(b[nb4][0]), "=r"(b[nb4][1]), "=r"(b[nb4][2]), "=r"(b[nb4][3])
                         : "r"(addr));
        }
#pragma unroll
        for (int nbb = 0; nbb < 8; nbb++)
            mma_fp16(acc[nbb], a, b[nbb >> 1][(nbb & 1) * 2], b[nbb >> 1][(nbb & 1) * 2 + 1]);
    }

    int g = lane >> 2, tg = lane & 3;
#pragma unroll
    for (int nbb = 0; nbb < 8; nbb++) {
        int rowl = wm + g;
        int nl = wn + nbb * 8 + tg * 2;
        float* c = acc[nbb];
        *(float2*)&sD[rowl * 132 + nl] = make_float2(c[0], c[1]);
        *(float2*)&sD[(rowl + 8) * 132 + nl] = make_float2(c[2], c[3]);
    }
    __syncthreads();

    float br  = bih[lane] + bhh[lane];
    float bz  = bih[32 + lane] + bhh[32 + lane];
    float bin = bih[64 + lane];
    float bhn = bhh[64 + lane];
#pragma unroll
    for (int l = 0; l < 8; l++) {
        int idx = tid + l * 256;
        int n = idx >> 5, o = idx & 31;
        int node = base + n;
        if (node < NN) {
            const float* d = &sD[n * 132];
            float r = 1.f / (1.f + expf(-(d[o] + br)));
            float z = 1.f / (1.f + expf(-(d[32 + o] + bz)));
            float nv = tanhf(d[64 + o] + bin + r * (d[96 + o] + bhn));
            float h = shf[n * 32 + o];
            g_x[node * DIM + o] = (1.f - z) * nv + z * h;
        }
    }
}

// ---------------- fused Set2Set: one block per graph, all 3 steps + writeout ----------------
__global__ void __launch_bounds__(128) s2s_kernel(const int* __restrict__ gidx,
                                                  const float* __restrict__ bih,
                                                  const float* __restrict__ bhh,
                                                  float* __restrict__ out) {
    int g = blockIdx.x;
    int tid = threadIdx.x, lane = tid & 31, w = tid >> 5;
    __shared__ float sq[64];
    __shared__ float sh[DIM], sc[DIM];
    __shared__ float sgate[128];
    __shared__ float red[4], sr[4][DIM], sd[4];
    __shared__ int   sse[2];

    if (tid < 2) {
        int target = g + tid;
        int lo = 0, hi = NN;
        while (lo < hi) { int mid = (lo + hi) >> 1; if (gidx[mid] < target) lo = mid + 1; else hi = mid; }
        sse[tid] = lo;
    }
    if (tid < 64) sq[tid] = 0.f;
    if (tid < DIM) { sh[tid] = 0.f; sc[tid] = 0.f; }
    __syncthreads();
    int s = sse[0], e = sse[1];

    float bsum = bih[tid] + bhh[tid];

    for (int step = 0; step < 3; step++) {
        float gv = bsum;
        for (int i = 0; i < 64; i++) gv = fmaf(sq[i], g_lwihT[i * 128 + tid], gv);
        for (int i = 0; i < DIM; i++) gv = fmaf(sh[i], g_lwhhT[i * 128 + tid], gv);
        sgate[tid] = gv;
        __syncthreads();
        if (tid < DIM) {
            float si = 1.f / (1.f + expf(-sgate[tid]));
            float sf = 1.f / (1.f + expf(-sgate[32 + tid]));
            float gg = tanhf(sgate[64 + tid]);
            float so = 1.f / (1.f + expf(-sgate[96 + tid]));
            float cc = sf * sc[tid] + si * gg;
            sc[tid] = cc;
            sh[tid] = so * tanhf(cc);
        }
        __syncthreads();

        float qv = sh[lane];
        float mx = -INFINITY;
        for (int n = s + w; n < e; n += 4) {
            float v = g_x[n * DIM + lane] * qv;
#pragma unroll
            for (int off = 16; off; off >>= 1) v += __shfl_xor_sync(0xffffffffu, v, off);
            mx = fmaxf(mx, v);
        }
        if (lane == 0) red[w] = mx;
        __syncthreads();
        mx = fmaxf(fmaxf(red[0], red[1]), fmaxf(red[2], red[3]));
        float denom = 0.f, racc = 0.f;
        for (int n = s + w; n < e; n += 4) {
            float xo = g_x[n * DIM + lane];
            float v = xo * qv;
#pragma unroll
            for (int off = 16; off; off >>= 1) v += __shfl_xor_sync(0xffffffffu, v, off);
            float ex = __expf(v - mx);
            denom += ex;
            racc = fmaf(ex, xo, racc);
        }
        sr[w][lane] = racc;
        if (lane == 0) sd[w] = denom;
        __syncthreads();
        if (w == 0) {
            float r = sr[0][lane] + sr[1][lane] + sr[2][lane] + sr[3][lane];
            float d = sd[0] + sd[1] + sd[2] + sd[3];
            r = (d > 0.f) ? r / d : 0.f;
            sq[lane] = sh[lane];
            sq[32 + lane] = r;
        }
        __syncthreads();
    }

    if (tid < 64) out[g * 64 + tid] = sq[tid];
    int cnt = (e - s) * DIM;
    const float* xs = g_x + s * DIM;
    float* od = out + NB * 64 + s * DIM;
    for (int i = tid; i < cnt; i += 128) od[i] = xs[i];
}

// ---------------- launch ----------------
extern "C" void kernel_launch(void* const* d_in, const int* in_sizes, int n_in,
                              void* d_out, int out_size) {
    const float* nf        = (const float*)d_in[0];
    const float* ef        = (const float*)d_in[1];
    const float* lin0_w    = (const float*)d_in[2];
    const float* lin0_b    = (const float*)d_in[3];
    const float* nn_w1     = (const float*)d_in[4];
    const float* nn_b1     = (const float*)d_in[5];
    const float* nn_w2     = (const float*)d_in[6];
    const float* nn_b2     = (const float*)d_in[7];
    const float* conv_bias = (const float*)d_in[8];
    const float* gru_wih   = (const float*)d_in[9];
    const float* gru_whh   = (const float*)d_in[10];
    const float* gru_bih   = (const float*)d_in[11];
    const float* gru_bhh   = (const float*)d_in[12];
    const float* lstm_wih  = (const float*)d_in[13];
    const float* lstm_whh  = (const float*)d_in[14];
    const float* lstm_bih  = (const float*)d_in[15];
    const float* lstm_bhh  = (const float*)d_in[16];
    const int*   ei        = (const int*)d_in[17];
    const int*   gidx      = (const int*)d_in[18];

    static cudaStream_t s2 = 0;
    static cudaEvent_t evA = 0, evB = 0;
    if (!s2) {
        cudaFuncSetAttribute(gemm_fused_kernel, cudaFuncAttributeMaxDynamicSharedMemorySize,
                             SMEM_GEMM_TOTAL);
        cudaFuncSetAttribute(gru_mma_kernel, cudaFuncAttributeMaxDynamicSharedMemorySize,
                             GRU_SMEM);
        cudaStreamCreateWithFlags(&s2, cudaStreamNonBlocking);
        cudaEventCreateWithFlags(&evA, cudaEventDisableTiming);
        cudaEventCreateWithFlags(&evB, cudaEventDisableTiming);
    }

    prep_kernel<<<512, 256>>>(lin0_w, nn_w1, gru_wih, gru_whh, lstm_wih, lstm_whh, nn_w2, nn_b2);
    cudaEventRecord(evA, 0);
    cudaStreamWaitEvent(s2, evA, 0);
    lin0_kernel<<<(NN + 63) / 64, 256, 0, s2>>>(nf, lin0_b);   // zeroes g_cnt / g_acc
    deg_kernel<<<(NE + 255) / 256, 256, 0, s2>>>(ei);
    cudaEventRecord(evB, s2);
    gemm_fused_kernel<<<MPAD / 64, 256, SMEM_GEMM_TOTAL>>>(ef, nn_b1);  // overlaps lin0/deg
    cudaStreamWaitEvent(0, evB, 0);

    for (int t = 0; t < 3; t++) {
        conv_kernel<<<NE / 8, 256>>>(ei);
        gru_mma_kernel<<<(NN + 63) / 64, 256, GRU_SMEM>>>(conv_bias, gru_bih, gru_bhh);
    }

    s2s_kernel<<<NB, 128>>>(gidx, lstm_bih, lstm_bhh, (float*)d_out);
}